// round 6
// baseline (speedup 1.0000x reference)
#include <cuda_runtime.h>

// Modelev12: 2-layer LSTM, H=48, B=4096, T=512, F=64
// R5: 384 threads (3 warps/SMSP) for latency hiding + parallel output head.
#define H      48
#define TOBS   512
#define FPRED  64
#define TTOT   (TOBS + FPRED)     // 576
#define BATCH  4096
#define MB     32                 // batch rows per CTA
#define NCTA   (BATCH / MB)       // 128
#define NTHR   384                // 12 warps = 4 batch-groups x 3 row-thirds

typedef unsigned long long ull;

// shared layout (float offsets; all vector-accessed blocks 16B-aligned)
#define OFF_WT0 0                        // [48*192]  Whh0^T   (WT0[k*192+r])
#define OFF_WT1 (OFF_WT0 + 48*192)       // [96*192]  [Wih1|Whh1]^T
#define OFF_WI0 (OFF_WT1 + 96*192)       // [192]
#define OFF_B0  (OFF_WI0 + 192)          // [192]
#define OFF_B1  (OFF_B0 + 192)           // [192]
#define OFF_WL  (OFF_B1 + 192)           // [48]
#define OFF_HC2 (OFF_WL + 48)            // [96][36]  h state, HC2[k*36+b]
#define OFF_H1  (OFF_HC2 + 96*36)        // [32*49]   plain h1 for head
#define OFF_XC  (OFF_H1 + 32*49)         // [32]      even offset -> LDS.64 OK
#define OFF_GT  (OFF_XC + 32)            // [32][192] gate pre-activations
#define SMEM_FLOATS (OFF_GT + 32*192)
#define SMEM_BYTES  (SMEM_FLOATS * 4)

__device__ __forceinline__ ull ffma2(ull a, ull b, ull c) {
    ull d;
    asm("fma.rn.f32x2 %0, %1, %2, %3;" : "=l"(d) : "l"(a), "l"(b), "l"(c));
    return d;
}
__device__ __forceinline__ ull pack1(float v) {            // {v, v}
    ull d; asm("mov.b64 %0, {%1, %1};" : "=l"(d) : "f"(v)); return d;
}
__device__ __forceinline__ void unpack2(ull v, float& lo, float& hi) {
    asm("mov.b64 {%0, %1}, %2;" : "=f"(lo), "=f"(hi) : "l"(v));
}
__device__ __forceinline__ float fsig(float xv) {
    float e = __expf(-xv);
    return __fdividef(1.0f, 1.0f + e);
}
__device__ __forceinline__ float ftanh(float xv) {
    float a = fabsf(xv);
    float e = __expf(-2.0f * a);
    float r = __fdividef(1.0f - e, 1.0f + e);
    return copysignf(r, xv);
}

__global__ void __launch_bounds__(NTHR, 1) lstm576_bp3_kernel(
    const float* __restrict__ x,
    const float* __restrict__ wih0, const float* __restrict__ whh0,
    const float* __restrict__ bih0, const float* __restrict__ bhh0,
    const float* __restrict__ wih1, const float* __restrict__ whh1,
    const float* __restrict__ bih1, const float* __restrict__ bhh1,
    const float* __restrict__ wlin, const float* __restrict__ blin,
    float* __restrict__ out)
{
    extern __shared__ float sm[];
    float* WT0 = sm + OFF_WT0;
    float* WT1 = sm + OFF_WT1;
    float* WI0 = sm + OFF_WI0;
    float* B0s = sm + OFF_B0;
    float* B1s = sm + OFF_B1;
    float* WLs = sm + OFF_WL;
    float* HC2 = sm + OFF_HC2;   // HC2[k*36 + b]
    float* H1s = sm + OFF_H1;
    float* XCs = sm + OFF_XC;
    float* GTs = sm + OFF_GT;

    const int tid = threadIdx.x;
    const int rg  = tid & 31;
    const int w   = tid >> 5;        // 0..11
    const int bg  = w & 3;           // batch group: batches 8*bg .. 8*bg+7
    const int rt  = w >> 2;          // row third: rows 64*rt .. 64*rt+63
    const int rbase = 64 * rt + rg;  // rows rbase, rbase+32
    const int gb0 = blockIdx.x * MB;
    const int bloc = 8 * bg;         // local batch base for this warp

    // head mapping: 8 threads per batch row
    const int hb = tid >> 3;         // 0..47 (valid if < 32)
    const int hk = (tid & 7) * 6;    // k chunk base

    // ---- one-time staging ----
    for (int i = tid; i < 48 * 192; i += NTHR) {
        int k = i / 192, r = i - k * 192;
        WT0[i] = whh0[r * 48 + k];
    }
    for (int i = tid; i < 96 * 192; i += NTHR) {
        int k = i / 192, r = i - k * 192;
        WT1[i] = (k < 48) ? wih1[r * 48 + k] : whh1[r * 48 + (k - 48)];
    }
    for (int i = tid; i < 192; i += NTHR) {
        WI0[i] = wih0[i];
        B0s[i] = bih0[i] + bhh0[i];
        B1s[i] = bih1[i] + bhh1[i];
    }
    if (tid < 48) WLs[tid] = wlin[tid];
    for (int i = tid; i < 96 * 36; i += NTHR) HC2[i] = 0.0f;
    for (int i = tid; i < 32 * 49; i += NTHR) H1s[i] = 0.0f;
    if (tid < MB) XCs[tid] = x[(size_t)(gb0 + tid) * TOBS];
    const float blv = blin[0];

    // activation ownership: element e = b*48 + j, thread owns e = tid + 384*i
    float c0r[4], c1r[4];
    int eb[4], ej[4];
#pragma unroll
    for (int i = 0; i < 4; i++) {
        c0r[i] = 0.0f; c1r[i] = 0.0f;
        int e = tid + NTHR * i;
        eb[i] = e / 48; ej[i] = e - 48 * eb[i];
    }
    __syncthreads();

    ull acc2[2][4];   // [row m][batch pair bp]

    for (int t = 0; t < TTOT; t++) {
        // prefetch next observed input (only head-writer threads need it)
        float xnext = 0.0f;
        if ((tid & 7) == 0 && hb < MB && (t + 1) < TOBS)
            xnext = x[(size_t)(gb0 + hb) * TOBS + (t + 1)];

        // ============ layer 0: gates0 = Whh0 @ h0 + Wih0*x + b ============
        {
            ull x2[4];
#pragma unroll
            for (int bp = 0; bp < 4; bp++)
                x2[bp] = *(const ull*)(XCs + bloc + 2 * bp);
#pragma unroll
            for (int m = 0; m < 2; m++) {
                int r = rbase + 32 * m;
                ull wi = pack1(WI0[r]);
                ull bs = pack1(B0s[r]);
#pragma unroll
                for (int bp = 0; bp < 4; bp++)
                    acc2[m][bp] = ffma2(wi, x2[bp], bs);
            }
#pragma unroll 4
            for (int kt = 0; kt < 48; kt += 4) {
                ulonglong2 ha[4], hb2[4];
#pragma unroll
                for (int d = 0; d < 4; d++) {
                    const float* hp = HC2 + (kt + d) * 36 + bloc;
                    ha[d]  = *(const ulonglong2*)(hp);       // bp 0,1
                    hb2[d] = *(const ulonglong2*)(hp + 4);   // bp 2,3
                }
#pragma unroll
                for (int d = 0; d < 4; d++) {
                    ull w2[2];
#pragma unroll
                    for (int m = 0; m < 2; m++)
                        w2[m] = pack1(WT0[(kt + d) * 192 + rbase + 32 * m]);
#pragma unroll
                    for (int m = 0; m < 2; m++) {
                        acc2[m][0] = ffma2(w2[m], ha[d].x,  acc2[m][0]);
                        acc2[m][1] = ffma2(w2[m], ha[d].y,  acc2[m][1]);
                        acc2[m][2] = ffma2(w2[m], hb2[d].x, acc2[m][2]);
                        acc2[m][3] = ffma2(w2[m], hb2[d].y, acc2[m][3]);
                    }
                }
            }
#pragma unroll
            for (int m = 0; m < 2; m++) {
                int r = rbase + 32 * m;
#pragma unroll
                for (int bp = 0; bp < 4; bp++) {
                    float g0, g1; unpack2(acc2[m][bp], g0, g1);
                    GTs[(bloc + 2 * bp)     * 192 + r] = g0;
                    GTs[(bloc + 2 * bp + 1) * 192 + r] = g1;
                }
            }
        }
        __syncthreads();

        // ---- layer 0 activations (c in regs, h -> HC2 rows 0..47) ----
#pragma unroll
        for (int i = 0; i < 4; i++) {
            const float* g4 = GTs + eb[i] * 192 + ej[i];
            float ii = fsig(g4[0]);
            float ff = fsig(g4[48]);
            float gg = ftanh(g4[96]);
            float oo = fsig(g4[144]);
            float c  = fmaf(ff, c0r[i], ii * gg);
            c0r[i]   = c;
            HC2[ej[i] * 36 + eb[i]] = oo * ftanh(c);
        }
        __syncthreads();

        // ============ layer 1: gates1 = [Wih1|Whh1] @ [h0; h1] + b ============
        {
#pragma unroll
            for (int m = 0; m < 2; m++) {
                ull bs = pack1(B1s[rbase + 32 * m]);
#pragma unroll
                for (int bp = 0; bp < 4; bp++) acc2[m][bp] = bs;
            }
#pragma unroll 4
            for (int kt = 0; kt < 96; kt += 4) {
                ulonglong2 ha[4], hb2[4];
#pragma unroll
                for (int d = 0; d < 4; d++) {
                    const float* hp = HC2 + (kt + d) * 36 + bloc;
                    ha[d]  = *(const ulonglong2*)(hp);
                    hb2[d] = *(const ulonglong2*)(hp + 4);
                }
#pragma unroll
                for (int d = 0; d < 4; d++) {
                    ull w2[2];
#pragma unroll
                    for (int m = 0; m < 2; m++)
                        w2[m] = pack1(WT1[(kt + d) * 192 + rbase + 32 * m]);
#pragma unroll
                    for (int m = 0; m < 2; m++) {
                        acc2[m][0] = ffma2(w2[m], ha[d].x,  acc2[m][0]);
                        acc2[m][1] = ffma2(w2[m], ha[d].y,  acc2[m][1]);
                        acc2[m][2] = ffma2(w2[m], hb2[d].x, acc2[m][2]);
                        acc2[m][3] = ffma2(w2[m], hb2[d].y, acc2[m][3]);
                    }
                }
            }
#pragma unroll
            for (int m = 0; m < 2; m++) {
                int r = rbase + 32 * m;
#pragma unroll
                for (int bp = 0; bp < 4; bp++) {
                    float g0, g1; unpack2(acc2[m][bp], g0, g1);
                    GTs[(bloc + 2 * bp)     * 192 + r] = g0;
                    GTs[(bloc + 2 * bp + 1) * 192 + r] = g1;
                }
            }
        }
        __syncthreads();

        // ---- layer 1 activations (h -> HC2 rows 48..95 + H1s for head) ----
#pragma unroll
        for (int i = 0; i < 4; i++) {
            const float* g4 = GTs + eb[i] * 192 + ej[i];
            float ii = fsig(g4[0]);
            float ff = fsig(g4[48]);
            float gg = ftanh(g4[96]);
            float oo = fsig(g4[144]);
            float c  = fmaf(ff, c1r[i], ii * gg);
            c1r[i]   = c;
            float h  = oo * ftanh(c);
            HC2[(48 + ej[i]) * 36 + eb[i]] = h;
            H1s[eb[i] * 49 + ej[i]] = h;
        }
        __syncthreads();

        // ---- output head: 8 threads per batch row, shfl reduce ----
        if (hb < MB) {
            const float* h1 = H1s + hb * 49 + hk;
            const float* wl = WLs + hk;
            float s = 0.f;
#pragma unroll
            for (int k = 0; k < 6; k++) s = fmaf(h1[k], wl[k], s);
            s += __shfl_xor_sync(0xFFFFFFFFu, s, 1);
            s += __shfl_xor_sync(0xFFFFFFFFu, s, 2);
            s += __shfl_xor_sync(0xFFFFFFFFu, s, 4);
            if ((tid & 7) == 0) {
                s += blv;
                out[(size_t)(gb0 + hb) * TTOT + t] = s;
                XCs[hb] = ((t + 1) < TOBS) ? xnext : s;
            }
        }
        __syncthreads();
    }
}

extern "C" void kernel_launch(void* const* d_in, const int* in_sizes, int n_in,
                              void* d_out, int out_size)
{
    (void)in_sizes; (void)n_in; (void)out_size;
    const float* x    = (const float*)d_in[0];
    const float* wih0 = (const float*)d_in[1];
    const float* whh0 = (const float*)d_in[2];
    const float* bih0 = (const float*)d_in[3];
    const float* bhh0 = (const float*)d_in[4];
    const float* wih1 = (const float*)d_in[5];
    const float* whh1 = (const float*)d_in[6];
    const float* bih1 = (const float*)d_in[7];
    const float* bhh1 = (const float*)d_in[8];
    const float* wlin = (const float*)d_in[9];
    const float* blin = (const float*)d_in[10];
    float* out = (float*)d_out;

    cudaFuncSetAttribute(lstm576_bp3_kernel,
                         cudaFuncAttributeMaxDynamicSharedMemorySize, SMEM_BYTES);
    lstm576_bp3_kernel<<<NCTA, NTHR, SMEM_BYTES>>>(
        x, wih0, whh0, bih0, bhh0, wih1, whh1, bih1, bhh1, wlin, blin, out);
}

// round 7
// speedup vs baseline: 1.2198x; 1.2198x over previous
#include <cuda_runtime.h>

// Modelev12: 2-layer LSTM, H=48, B=4096, T=512, F=64
// R6: fully warp-independent design — each warp owns 4 batches end-to-end.
// No __syncthreads in the time loop; warp-private SMEM regions; row-paired
// weights (LDS.64) with (i,g)/(f,o) packed gate pairs; in-warp fused head.
#define H      48
#define TOBS   512
#define FPRED  64
#define TTOT   (TOBS + FPRED)     // 576
#define BATCH  4096
#define MB     32                 // batch rows per CTA
#define NCTA   (BATCH / MB)       // 128
#define NTHR   256                // 8 warps x 4 batches each

typedef unsigned long long ull;

// float-offset shared layout (ull regions at even offsets, float4 at x4 offsets)
#define OFF_WTP0 0                       // ull[48*96]  {Whh0[q][k], Whh0[q+96][k]}
#define OFF_WTP1 9216                    // ull[96*96]  layer-1 [Wih1|Whh1] row-paired
#define OFF_WI0P 27648                   // ull[96]
#define OFF_B0P  27840                   // ull[96]
#define OFF_B1P  28032                   // ull[96]
#define OFF_HW   28224                   // 8 warps x [96k][4b] floats (384 each)
#define OFF_XCW  31296                   // 8 warps x 8 floats
#define OFF_GTP  31360                   // 8 warps x 4*GSTR ull
#define GSTR     101                     // ull stride per batch in gate buffer
#define GWARP    (4 * GSTR)              // 404 ull = 808 floats per warp
#define SMEM_FLOATS (OFF_GTP + 8 * 2 * GWARP)
#define SMEM_BYTES  (SMEM_FLOATS * 4)

__device__ __forceinline__ ull ffma2(ull a, ull b, ull c) {
    ull d;
    asm("fma.rn.f32x2 %0, %1, %2, %3;" : "=l"(d) : "l"(a), "l"(b), "l"(c));
    return d;
}
__device__ __forceinline__ ull pack1(float v) {            // {v, v}
    ull d; asm("mov.b64 %0, {%1, %1};" : "=l"(d) : "f"(v)); return d;
}
__device__ __forceinline__ ull pack2(float lo, float hi) {
    ull d; asm("mov.b64 %0, {%1, %2};" : "=l"(d) : "f"(lo), "f"(hi)); return d;
}
__device__ __forceinline__ float fsig(float xv) {
    float e = __expf(-xv);
    return __fdividef(1.0f, 1.0f + e);
}
__device__ __forceinline__ float ftanh(float xv) {
    float a = fabsf(xv);
    float e = __expf(-2.0f * a);
    float r = __fdividef(1.0f - e, 1.0f + e);
    return copysignf(r, xv);
}

__global__ void __launch_bounds__(NTHR, 1) lstm576_wi_kernel(
    const float* __restrict__ x,
    const float* __restrict__ wih0, const float* __restrict__ whh0,
    const float* __restrict__ bih0, const float* __restrict__ bhh0,
    const float* __restrict__ wih1, const float* __restrict__ whh1,
    const float* __restrict__ bih1, const float* __restrict__ bhh1,
    const float* __restrict__ wlin, const float* __restrict__ blin,
    float* __restrict__ out)
{
    extern __shared__ float sm[];
    ull* WTP0 = (ull*)(sm + OFF_WTP0);
    ull* WTP1 = (ull*)(sm + OFF_WTP1);
    ull* WI0P = (ull*)(sm + OFF_WI0P);
    ull* B0P  = (ull*)(sm + OFF_B0P);
    ull* B1P  = (ull*)(sm + OFF_B1P);

    const int tid  = threadIdx.x;
    const int lane = tid & 31;
    const int w    = tid >> 5;           // warp 0..7
    const int m8   = lane & 7;           // 8-lane segment position
    const int lb   = lane >> 3;          // local batch 0..3 (act/head)
    const int gb0  = blockIdx.x * MB;
    const int gbat = gb0 + 4 * w + lb;   // this lane's act/head batch

    float* HWw  = sm + OFF_HW  + w * 384;     // [96][4] h state (this warp)
    float* XCw  = sm + OFF_XCW + w * 8;       // 4 inputs (this warp)
    ull*   GTPw = (ull*)(sm + OFF_GTP) + w * GWARP;  // [4][GSTR] gate pairs

    // ---- one-time staging (cooperative, then one block sync) ----
    for (int i = tid; i < 48 * 96; i += NTHR) {
        int k = i / 96, q = i - k * 96;
        WTP0[i] = pack2(whh0[q * 48 + k], whh0[(q + 96) * 48 + k]);
    }
    for (int i = tid; i < 96 * 96; i += NTHR) {
        int k = i / 96, q = i - k * 96;
        float v0 = (k < 48) ? wih1[q * 48 + k] : whh1[q * 48 + (k - 48)];
        float v1 = (k < 48) ? wih1[(q + 96) * 48 + k] : whh1[(q + 96) * 48 + (k - 48)];
        WTP1[i] = pack2(v0, v1);
    }
    if (tid < 96) {
        WI0P[tid] = pack2(wih0[tid], wih0[tid + 96]);
        B0P[tid]  = pack2(bih0[tid] + bhh0[tid], bih0[tid + 96] + bhh0[tid + 96]);
        B1P[tid]  = pack2(bih1[tid] + bhh1[tid], bih1[tid + 96] + bhh1[tid + 96]);
    }
    for (int i = tid; i < 8 * 384; i += NTHR) sm[OFF_HW + i] = 0.0f;   // h = 0
    if (m8 == 0) XCw[lb] = x[(size_t)gbat * TOBS];                     // x[:,0]
    const float blv = blin[0];

    // per-lane constants: head weights for j = m8*6 + i
    float wlr[6];
#pragma unroll
    for (int i = 0; i < 6; i++) wlr[i] = wlin[m8 * 6 + i];

    float c0r[6], c1r[6];
#pragma unroll
    for (int i = 0; i < 6; i++) { c0r[i] = 0.0f; c1r[i] = 0.0f; }

    __syncthreads();   // only block-wide sync: weights staged

    ull acc[3][4];     // [row-pair chunk pp][batch b]

    for (int t = 0; t < TTOT; t++) {
        // prefetch next observed input (one lane per batch)
        float xnext = 0.0f;
        if (m8 == 0 && (t + 1) < TOBS)
            xnext = x[(size_t)gbat * TOBS + (t + 1)];

        // ============ layer 0 matvec: 192 rows x (x + 48 h0) ============
        {
            float4 x4 = *(const float4*)XCw;
            ull xx[4] = { pack1(x4.x), pack1(x4.y), pack1(x4.z), pack1(x4.w) };
#pragma unroll
            for (int pp = 0; pp < 3; pp++) {
                ull wi = WI0P[32 * pp + lane];
                ull bs = B0P[32 * pp + lane];
#pragma unroll
                for (int b = 0; b < 4; b++) acc[pp][b] = ffma2(wi, xx[b], bs);
            }
#pragma unroll 2
            for (int kt = 0; kt < 48; kt += 4) {
                float4 hq[4];
#pragma unroll
                for (int d = 0; d < 4; d++)
                    hq[d] = *(const float4*)(HWw + (kt + d) * 4);
#pragma unroll
                for (int d = 0; d < 4; d++) {
                    ull w2[3];
#pragma unroll
                    for (int pp = 0; pp < 3; pp++)
                        w2[pp] = WTP0[(kt + d) * 96 + 32 * pp + lane];
                    ull hh[4] = { pack1(hq[d].x), pack1(hq[d].y),
                                  pack1(hq[d].z), pack1(hq[d].w) };
#pragma unroll
                    for (int pp = 0; pp < 3; pp++)
#pragma unroll
                        for (int b = 0; b < 4; b++)
                            acc[pp][b] = ffma2(w2[pp], hh[b], acc[pp][b]);
                }
            }
#pragma unroll
            for (int pp = 0; pp < 3; pp++)
#pragma unroll
                for (int b = 0; b < 4; b++)
                    GTPw[b * GSTR + 32 * pp + lane] = acc[pp][b];
        }
        __syncwarp();

        // ---- layer 0 activations: pair j = (i_j, g_j), pair j+48 = (f_j, o_j) ----
#pragma unroll
        for (int i = 0; i < 6; i++) {
            int j = m8 * 6 + i;
            float2 ig = *(const float2*)(GTPw + lb * GSTR + j);
            float2 fo = *(const float2*)(GTPw + lb * GSTR + 48 + j);
            float ii = fsig(ig.x), gg = ftanh(ig.y);
            float ff = fsig(fo.x), oo = fsig(fo.y);
            float c = fmaf(ff, c0r[i], ii * gg);
            c0r[i] = c;
            HWw[j * 4 + lb] = oo * ftanh(c);
        }
        __syncwarp();

        // ============ layer 1 matvec: 192 rows x (48 h0_new + 48 h1_old) ============
        {
#pragma unroll
            for (int pp = 0; pp < 3; pp++) {
                ull bs = B1P[32 * pp + lane];
#pragma unroll
                for (int b = 0; b < 4; b++) acc[pp][b] = bs;
            }
#pragma unroll 2
            for (int kt = 0; kt < 96; kt += 4) {
                float4 hq[4];
#pragma unroll
                for (int d = 0; d < 4; d++)
                    hq[d] = *(const float4*)(HWw + (kt + d) * 4);
#pragma unroll
                for (int d = 0; d < 4; d++) {
                    ull w2[3];
#pragma unroll
                    for (int pp = 0; pp < 3; pp++)
                        w2[pp] = WTP1[(kt + d) * 96 + 32 * pp + lane];
                    ull hh[4] = { pack1(hq[d].x), pack1(hq[d].y),
                                  pack1(hq[d].z), pack1(hq[d].w) };
#pragma unroll
                    for (int pp = 0; pp < 3; pp++)
#pragma unroll
                        for (int b = 0; b < 4; b++)
                            acc[pp][b] = ffma2(w2[pp], hh[b], acc[pp][b]);
                }
            }
#pragma unroll
            for (int pp = 0; pp < 3; pp++)
#pragma unroll
                for (int b = 0; b < 4; b++)
                    GTPw[b * GSTR + 32 * pp + lane] = acc[pp][b];
        }
        __syncwarp();

        // ---- layer 1 activations + fused in-warp head ----
        float s = 0.0f;
#pragma unroll
        for (int i = 0; i < 6; i++) {
            int j = m8 * 6 + i;
            float2 ig = *(const float2*)(GTPw + lb * GSTR + j);
            float2 fo = *(const float2*)(GTPw + lb * GSTR + 48 + j);
            float ii = fsig(ig.x), gg = ftanh(ig.y);
            float ff = fsig(fo.x), oo = fsig(fo.y);
            float c = fmaf(ff, c1r[i], ii * gg);
            c1r[i] = c;
            float h = oo * ftanh(c);
            HWw[(48 + j) * 4 + lb] = h;
            s = fmaf(h, wlr[i], s);
        }
        // 8-lane butterfly reduce (lanes of same batch)
        s += __shfl_xor_sync(0xFFFFFFFFu, s, 1);
        s += __shfl_xor_sync(0xFFFFFFFFu, s, 2);
        s += __shfl_xor_sync(0xFFFFFFFFu, s, 4);
        if (m8 == 0) {
            s += blv;
            out[(size_t)gbat * TTOT + t] = s;
            XCw[lb] = ((t + 1) < TOBS) ? xnext : s;
        }
        __syncwarp();
    }
}

extern "C" void kernel_launch(void* const* d_in, const int* in_sizes, int n_in,
                              void* d_out, int out_size)
{
    (void)in_sizes; (void)n_in; (void)out_size;
    const float* x    = (const float*)d_in[0];
    const float* wih0 = (const float*)d_in[1];
    const float* whh0 = (const float*)d_in[2];
    const float* bih0 = (const float*)d_in[3];
    const float* bhh0 = (const float*)d_in[4];
    const float* wih1 = (const float*)d_in[5];
    const float* whh1 = (const float*)d_in[6];
    const float* bih1 = (const float*)d_in[7];
    const float* bhh1 = (const float*)d_in[8];
    const float* wlin = (const float*)d_in[9];
    const float* blin = (const float*)d_in[10];
    float* out = (float*)d_out;

    cudaFuncSetAttribute(lstm576_wi_kernel,
                         cudaFuncAttributeMaxDynamicSharedMemorySize, SMEM_BYTES);
    lstm576_wi_kernel<<<NCTA, NTHR, SMEM_BYTES>>>(
        x, wih0, whh0, bih0, bhh0, wih1, whh1, bih1, bhh1, wlin, blin, out);
}